// round 1
// baseline (speedup 1.0000x reference)
#include <cuda_runtime.h>

// SpectralGatingNetwork: out = Re(IFFT( W .* FFT(x, axis=-1) ))
// x: (8, 8, 2048, 512) fp32 ; W: (8, 2048, 512, 2) fp32 -> complex
// 131072 rows of length 512. Radix-8 Stockham FFT (3 stages each direction),
// 64 threads per row, 4 rows per 256-thread CTA.

#define D 512
#define ROWS_PER_BLOCK 4
#define THREADS (64 * ROWS_PER_BLOCK)
#define SPAD 576  // 512 + 512/8 padding

__device__ __forceinline__ float2 cadd(float2 a, float2 b) { return make_float2(a.x + b.x, a.y + b.y); }
__device__ __forceinline__ float2 csub(float2 a, float2 b) { return make_float2(a.x - b.x, a.y - b.y); }
__device__ __forceinline__ float2 cmul(float2 a, float2 b) {
    return make_float2(fmaf(a.x, b.x, -a.y * b.y), fmaf(a.x, b.y, a.y * b.x));
}

// multiply by e^{S * i * pi/2}:  S=-1 -> -i*z = (y, -x) ; S=+1 -> +i*z = (-y, x)
template <int S>
__device__ __forceinline__ float2 mulJ(float2 z) {
    return (S < 0) ? make_float2(z.y, -z.x) : make_float2(-z.y, z.x);
}

template <int S>
__device__ __forceinline__ void dft4(float2 x0, float2 x1, float2 x2, float2 x3, float2 o[4]) {
    float2 e0 = cadd(x0, x2), e1 = csub(x0, x2);
    float2 d0 = cadd(x1, x3), d1 = csub(x1, x3);
    o[0] = cadd(e0, d0);
    o[2] = csub(e0, d0);
    float2 jd1 = mulJ<S>(d1);
    o[1] = cadd(e1, jd1);
    o[3] = csub(e1, jd1);
}

// 8-point DFT with sign S (-1 forward, +1 inverse, no scaling)
template <int S>
__device__ __forceinline__ void dft8(const float2 a[8], float2 b[8]) {
    float2 e[4], o[4];
    dft4<S>(a[0], a[2], a[4], a[6], e);
    dft4<S>(a[1], a[3], a[5], a[7], o);
    const float r2 = 0.70710678118654752f;
    const float2 w1 = make_float2(r2, S * r2);
    const float2 w3 = make_float2(-r2, S * r2);
    float2 u1 = cmul(o[1], w1);
    float2 u2 = mulJ<S>(o[2]);
    float2 u3 = cmul(o[3], w3);
    b[0] = cadd(e[0], o[0]); b[4] = csub(e[0], o[0]);
    b[1] = cadd(e[1], u1);   b[5] = csub(e[1], u1);
    b[2] = cadd(e[2], u2);   b[6] = csub(e[2], u2);
    b[3] = cadd(e[3], u3);   b[7] = csub(e[3], u3);
}

// Apply Stockham twiddles: a[m] *= exp(S * 2*pi*i * k * m / M)
template <int S>
__device__ __forceinline__ void twiddle(float2 a[8], int k, float two_pi_over_M) {
    float ang = (float)S * two_pi_over_M * (float)k;
    float s, c;
    __sincosf(ang, &s, &c);
    float2 w = make_float2(c, s);
    float2 wm = w;
    a[1] = cmul(a[1], wm);
#pragma unroll
    for (int m = 2; m < 8; m++) {
        wm = cmul(wm, w);
        a[m] = cmul(a[m], wm);
    }
}

__device__ __forceinline__ int pad(int i) { return i + (i >> 3); }

__global__ void __launch_bounds__(THREADS, 3)
sgn_fft_kernel(const float* __restrict__ x,
               const float2* __restrict__ w,
               float* __restrict__ out,
               int wrow_mask) {
    __shared__ float sre[ROWS_PER_BLOCK][SPAD];
    __shared__ float sim[ROWS_PER_BLOCK][SPAD];

    const int tid = threadIdx.x;
    const int r = tid >> 6;      // row within block
    const int j = tid & 63;      // butterfly index within row (0..63)

    const long long row = (long long)blockIdx.x * ROWS_PER_BLOCK + r;
    const float* __restrict__ xrow = x + row * D;
    const float2* __restrict__ wrow = w + (long long)((int)(row & wrow_mask)) * D;
    float* __restrict__ orow = out + row * D;

    float* re = sre[r];
    float* im = sim[r];

    float2 a[8], b[8];

    // ---------------- forward FFT ----------------
    // stage 0 (L=1, k=0): read global, butterfly, write out[8j + t]
#pragma unroll
    for (int m = 0; m < 8; m++) a[m] = make_float2(xrow[j + 64 * m], 0.0f);
    dft8<-1>(a, b);
#pragma unroll
    for (int t = 0; t < 8; t++) {
        int p = pad(8 * j + t);
        re[p] = b[t].x; im[p] = b[t].y;
    }
    __syncthreads();

    // stage 1 (L=8): in[j + 64m] -> out[(j/8)*64 + (j%8) + 8t]
#pragma unroll
    for (int m = 0; m < 8; m++) {
        int p = pad(j + 64 * m);
        a[m] = make_float2(re[p], im[p]);
    }
    __syncthreads();
    {
        int k = j & 7;
        twiddle<-1>(a, k, 6.2831853071795865f / 64.0f);
        dft8<-1>(a, b);
        int blk = j >> 3;
#pragma unroll
        for (int t = 0; t < 8; t++) {
            int p = pad(blk * 64 + k + 8 * t);
            re[p] = b[t].x; im[p] = b[t].y;
        }
    }
    __syncthreads();

    // stage 2 (L=64): in[j + 64m] -> X[j + 64t] held in registers
#pragma unroll
    for (int m = 0; m < 8; m++) {
        int p = pad(j + 64 * m);
        a[m] = make_float2(re[p], im[p]);
    }
    __syncthreads();  // everyone done reading before inverse stage writes
    twiddle<-1>(a, j, 6.2831853071795865f / 512.0f);
    dft8<-1>(a, b);   // b[t] = X[j + 64t]

    // ---------------- spectral gating (in registers) ----------------
    // Y[j + 64t] = W[j + 64t] * X[j + 64t]
#pragma unroll
    for (int t = 0; t < 8; t++) {
        float2 wv = wrow[j + 64 * t];
        a[t] = cmul(wv, b[t]);   // a[m] is exactly the inverse stage-0 input in[j + 64m]
    }

    // ---------------- inverse FFT ----------------
    // stage 0 (L=1, k=0)
    dft8<1>(a, b);
#pragma unroll
    for (int t = 0; t < 8; t++) {
        int p = pad(8 * j + t);
        re[p] = b[t].x; im[p] = b[t].y;
    }
    __syncthreads();

    // stage 1 (L=8)
#pragma unroll
    for (int m = 0; m < 8; m++) {
        int p = pad(j + 64 * m);
        a[m] = make_float2(re[p], im[p]);
    }
    __syncthreads();
    {
        int k = j & 7;
        twiddle<1>(a, k, 6.2831853071795865f / 64.0f);
        dft8<1>(a, b);
        int blk = j >> 3;
#pragma unroll
        for (int t = 0; t < 8; t++) {
            int p = pad(blk * 64 + k + 8 * t);
            re[p] = b[t].x; im[p] = b[t].y;
        }
    }
    __syncthreads();

    // stage 2 (L=64): output y[j + 64t], take real part, scale 1/512
#pragma unroll
    for (int m = 0; m < 8; m++) {
        int p = pad(j + 64 * m);
        a[m] = make_float2(re[p], im[p]);
    }
    twiddle<1>(a, j, 6.2831853071795865f / 512.0f);
    dft8<1>(a, b);
#pragma unroll
    for (int t = 0; t < 8; t++) {
        orow[j + 64 * t] = b[t].x * (1.0f / 512.0f);
    }
}

extern "C" void kernel_launch(void* const* d_in, const int* in_sizes, int n_in,
                              void* d_out, int out_size) {
    (void)n_in;
    const float* x = (const float*)d_in[0];
    // d_in[1] = mask (unused)
    const float2* w = (const float2*)d_in[2];
    float* out = (float*)d_out;

    // rows = B*H*L ; weight rows repeat every H*L (batch broadcast)
    const int rows = out_size / D;                 // 131072
    const int wrows = (in_sizes[2] / 2) / D;       // H*L = 16384
    const int wrow_mask = wrows - 1;               // power of two

    const int blocks = rows / ROWS_PER_BLOCK;
    sgn_fft_kernel<<<blocks, THREADS>>>(x, w, out, wrow_mask);
}

// round 2
// speedup vs baseline: 1.6294x; 1.6294x over previous
#include <cuda_runtime.h>

// SpectralGatingNetwork: out = Re(IFFT( W .* FFT(x, axis=-1) ))
// x: (8, 8, 2048, 512) fp32 ; W: (8, 2048, 512, 2) fp32
//
// Real-input optimization: for real x,
//   Re(IFFT(W .* FFT(x))) == IFFT(Weff .* FFT(x)),  Weff[k] = 0.5*(W[k] + conj(W[(N-k)%N]))
// and Weff is conjugate-symmetric, so packing two real rows z = x0 + i*x1 gives
//   IFFT(Weff .* FFT(z)) = y0 + i*y1   (both outputs from ONE complex FFT/IFFT pair).
//
// Grid: one CTA per (h,l); 4 batch-pairs (all 8 batches) per CTA, 64 threads/pair.
// W row fetched from DRAM once per CTA (L1-served for the 4 pairs).

#define D 512
#define PAIRS_PER_BLOCK 4
#define THREADS (64 * PAIRS_PER_BLOCK)
#define SPAD 576  // 512 + 512/8 padding

__device__ __forceinline__ float2 cadd(float2 a, float2 b) { return make_float2(a.x + b.x, a.y + b.y); }
__device__ __forceinline__ float2 csub(float2 a, float2 b) { return make_float2(a.x - b.x, a.y - b.y); }
__device__ __forceinline__ float2 cmul(float2 a, float2 b) {
    return make_float2(fmaf(a.x, b.x, -a.y * b.y), fmaf(a.x, b.y, a.y * b.x));
}

template <int S>
__device__ __forceinline__ float2 mulJ(float2 z) {
    return (S < 0) ? make_float2(z.y, -z.x) : make_float2(-z.y, z.x);
}

template <int S>
__device__ __forceinline__ void dft4(float2 x0, float2 x1, float2 x2, float2 x3, float2 o[4]) {
    float2 e0 = cadd(x0, x2), e1 = csub(x0, x2);
    float2 d0 = cadd(x1, x3), d1 = csub(x1, x3);
    o[0] = cadd(e0, d0);
    o[2] = csub(e0, d0);
    float2 jd1 = mulJ<S>(d1);
    o[1] = cadd(e1, jd1);
    o[3] = csub(e1, jd1);
}

template <int S>
__device__ __forceinline__ void dft8(const float2 a[8], float2 b[8]) {
    float2 e[4], o[4];
    dft4<S>(a[0], a[2], a[4], a[6], e);
    dft4<S>(a[1], a[3], a[5], a[7], o);
    const float r2 = 0.70710678118654752f;
    const float2 w1 = make_float2(r2, S * r2);
    const float2 w3 = make_float2(-r2, S * r2);
    float2 u1 = cmul(o[1], w1);
    float2 u2 = mulJ<S>(o[2]);
    float2 u3 = cmul(o[3], w3);
    b[0] = cadd(e[0], o[0]); b[4] = csub(e[0], o[0]);
    b[1] = cadd(e[1], u1);   b[5] = csub(e[1], u1);
    b[2] = cadd(e[2], u2);   b[6] = csub(e[2], u2);
    b[3] = cadd(e[3], u3);   b[7] = csub(e[3], u3);
}

template <int S>
__device__ __forceinline__ void twiddle(float2 a[8], int k, float two_pi_over_M) {
    float ang = (float)S * two_pi_over_M * (float)k;
    float s, c;
    __sincosf(ang, &s, &c);
    float2 w = make_float2(c, s);
    float2 wm = w;
    a[1] = cmul(a[1], wm);
#pragma unroll
    for (int m = 2; m < 8; m++) {
        wm = cmul(wm, w);
        a[m] = cmul(a[m], wm);
    }
}

__device__ __forceinline__ int pad(int i) { return i + (i >> 3); }

__global__ void __launch_bounds__(THREADS, 3)
sgn_fft_kernel(const float* __restrict__ x,
               const float2* __restrict__ w,
               float* __restrict__ out,
               int batch_stride)   // = (H*L)*D elements between consecutive batches
{
    __shared__ float sre[PAIRS_PER_BLOCK][SPAD];
    __shared__ float sim[PAIRS_PER_BLOCK][SPAD];

    const int tid = threadIdx.x;
    const int r = tid >> 6;      // batch-pair within block (0..3) -> batches 2r, 2r+1
    const int j = tid & 63;      // butterfly index within row (0..63)

    const int hl = blockIdx.x;   // (h,l) index, 0..16383
    const long long base = (long long)hl * D;
    const float* __restrict__ x0 = x + base + (long long)(2 * r) * batch_stride;
    const float* __restrict__ x1 = x0 + batch_stride;
    float* __restrict__ o0 = out + base + (long long)(2 * r) * batch_stride;
    float* __restrict__ o1 = o0 + batch_stride;
    const float2* __restrict__ wrow = w + base;

    float* re = sre[r];
    float* im = sim[r];

    float2 a[8], b[8];

    // ---------------- forward FFT of z = x0 + i*x1 ----------------
    // stage 0 (L=1): read global, butterfly, write out[8j + t]
#pragma unroll
    for (int m = 0; m < 8; m++) a[m] = make_float2(x0[j + 64 * m], x1[j + 64 * m]);
    dft8<-1>(a, b);
#pragma unroll
    for (int t = 0; t < 8; t++) {
        int p = pad(8 * j + t);
        re[p] = b[t].x; im[p] = b[t].y;
    }
    __syncthreads();

    // stage 1 (L=8): in[j + 64m] -> out[(j/8)*64 + (j%8) + 8t]
#pragma unroll
    for (int m = 0; m < 8; m++) {
        int p = pad(j + 64 * m);
        a[m] = make_float2(re[p], im[p]);
    }
    __syncthreads();
    {
        int k = j & 7;
        twiddle<-1>(a, k, 6.2831853071795865f / 64.0f);
        dft8<-1>(a, b);
        int blk = j >> 3;
#pragma unroll
        for (int t = 0; t < 8; t++) {
            int p = pad(blk * 64 + k + 8 * t);
            re[p] = b[t].x; im[p] = b[t].y;
        }
    }
    __syncthreads();

    // stage 2 (L=64): in[j + 64m] -> Z[j + 64t] held in registers
#pragma unroll
    for (int m = 0; m < 8; m++) {
        int p = pad(j + 64 * m);
        a[m] = make_float2(re[p], im[p]);
    }
    __syncthreads();  // everyone done reading before inverse stage writes
    twiddle<-1>(a, j, 6.2831853071795865f / 512.0f);
    dft8<-1>(a, b);   // b[t] = Z[j + 64t]

    // ---------------- spectral gating with Weff (in registers) ----------------
    // Weff[k] = 0.5*(W[k] + conj(W[(512-k)&511])); C[k] = Weff[k]*Z[k]
#pragma unroll
    for (int t = 0; t < 8; t++) {
        int k = j + 64 * t;
        int kc = (D - k) & (D - 1);
        float2 wk = wrow[k];
        float2 wkc = wrow[kc];
        float2 weff = make_float2(0.5f * (wk.x + wkc.x), 0.5f * (wk.y - wkc.y));
        a[t] = cmul(weff, b[t]);   // a[m] is exactly the inverse stage-0 input in[j + 64m]
    }

    // ---------------- inverse FFT ----------------
    dft8<1>(a, b);
#pragma unroll
    for (int t = 0; t < 8; t++) {
        int p = pad(8 * j + t);
        re[p] = b[t].x; im[p] = b[t].y;
    }
    __syncthreads();

    // stage 1 (L=8)
#pragma unroll
    for (int m = 0; m < 8; m++) {
        int p = pad(j + 64 * m);
        a[m] = make_float2(re[p], im[p]);
    }
    __syncthreads();
    {
        int k = j & 7;
        twiddle<1>(a, k, 6.2831853071795865f / 64.0f);
        dft8<1>(a, b);
        int blk = j >> 3;
#pragma unroll
        for (int t = 0; t < 8; t++) {
            int p = pad(blk * 64 + k + 8 * t);
            re[p] = b[t].x; im[p] = b[t].y;
        }
    }
    __syncthreads();

    // stage 2 (L=64): c[j + 64t]; y0 = Re(c), y1 = Im(c), scale 1/512
#pragma unroll
    for (int m = 0; m < 8; m++) {
        int p = pad(j + 64 * m);
        a[m] = make_float2(re[p], im[p]);
    }
    twiddle<1>(a, j, 6.2831853071795865f / 512.0f);
    dft8<1>(a, b);
#pragma unroll
    for (int t = 0; t < 8; t++) {
        o0[j + 64 * t] = b[t].x * (1.0f / 512.0f);
        o1[j + 64 * t] = b[t].y * (1.0f / 512.0f);
    }
}

extern "C" void kernel_launch(void* const* d_in, const int* in_sizes, int n_in,
                              void* d_out, int out_size) {
    (void)n_in;
    const float* x = (const float*)d_in[0];
    // d_in[1] = mask (unused)
    const float2* w = (const float2*)d_in[2];
    float* out = (float*)d_out;

    const int wrows = (in_sizes[2] / 2) / D;   // H*L = 16384
    const int batch_stride = wrows * D;        // elements between consecutive batches

    // one CTA per (h,l); each CTA handles all 8 batches as 4 complex-packed pairs
    sgn_fft_kernel<<<wrows, THREADS>>>(x, w, out, batch_stride);
}

// round 3
// speedup vs baseline: 1.9467x; 1.1948x over previous
#include <cuda_runtime.h>

// SpectralGatingNetwork: out = Re(IFFT( W .* FFT(x, axis=-1) ))
// Real-packing: z = x[b0] + i*x[b1], gate by conjugate-symmetric
// Weff[k] = 0.5*(W[k] + conj(W[(N-k)%N])) => y0 = Re, y1 = Im.
// Radix-8 Stockham, 64 threads/pair, 4 pairs (8 batches) per CTA, one CTA per (h,l).
// float2 shared memory + ping-pong buffers (4 barriers total).

#define D 512
#define PAIRS_PER_BLOCK 4
#define THREADS (64 * PAIRS_PER_BLOCK)
#define SPAD 576  // 512 + 512/8 padding (in float2 units)

__device__ __forceinline__ float2 cadd(float2 a, float2 b) { return make_float2(a.x + b.x, a.y + b.y); }
__device__ __forceinline__ float2 csub(float2 a, float2 b) { return make_float2(a.x - b.x, a.y - b.y); }
__device__ __forceinline__ float2 cmul(float2 a, float2 b) {
    return make_float2(fmaf(a.x, b.x, -a.y * b.y), fmaf(a.x, b.y, a.y * b.x));
}

template <int S>
__device__ __forceinline__ float2 mulJ(float2 z) {
    return (S < 0) ? make_float2(z.y, -z.x) : make_float2(-z.y, z.x);
}

template <int S>
__device__ __forceinline__ void dft4(float2 x0, float2 x1, float2 x2, float2 x3, float2 o[4]) {
    float2 e0 = cadd(x0, x2), e1 = csub(x0, x2);
    float2 d0 = cadd(x1, x3), d1 = csub(x1, x3);
    o[0] = cadd(e0, d0);
    o[2] = csub(e0, d0);
    float2 jd1 = mulJ<S>(d1);
    o[1] = cadd(e1, jd1);
    o[3] = csub(e1, jd1);
}

template <int S>
__device__ __forceinline__ void dft8(const float2 a[8], float2 b[8]) {
    float2 e[4], o[4];
    dft4<S>(a[0], a[2], a[4], a[6], e);
    dft4<S>(a[1], a[3], a[5], a[7], o);
    const float r2 = 0.70710678118654752f;
    const float2 w1 = make_float2(r2, S * r2);
    const float2 w3 = make_float2(-r2, S * r2);
    float2 u1 = cmul(o[1], w1);
    float2 u2 = mulJ<S>(o[2]);
    float2 u3 = cmul(o[3], w3);
    b[0] = cadd(e[0], o[0]); b[4] = csub(e[0], o[0]);
    b[1] = cadd(e[1], u1);   b[5] = csub(e[1], u1);
    b[2] = cadd(e[2], u2);   b[6] = csub(e[2], u2);
    b[3] = cadd(e[3], u3);   b[7] = csub(e[3], u3);
}

// a[m] *= exp(S * i * two_pi_over_M * k * m), log-depth power construction
template <int S>
__device__ __forceinline__ void twiddle8(float2 a[8], int k, float two_pi_over_M) {
    float ang = (float)S * two_pi_over_M * (float)k;
    float s1, c1, s4, c4;
    __sincosf(ang, &s1, &c1);
    __sincosf(4.0f * ang, &s4, &c4);
    float2 w1 = make_float2(c1, s1);
    float2 w4 = make_float2(c4, s4);
    float2 w2 = cmul(w1, w1);
    float2 w3 = cmul(w2, w1);
    float2 w5 = cmul(w4, w1);
    float2 w6 = cmul(w4, w2);
    float2 w7 = cmul(w4, w3);
    a[1] = cmul(a[1], w1);
    a[2] = cmul(a[2], w2);
    a[3] = cmul(a[3], w3);
    a[4] = cmul(a[4], w4);
    a[5] = cmul(a[5], w5);
    a[6] = cmul(a[6], w6);
    a[7] = cmul(a[7], w7);
}

__device__ __forceinline__ int pad(int i) { return i + (i >> 3); }

__global__ void __launch_bounds__(THREADS, 3)
sgn_fft_kernel(const float* __restrict__ x,
               const float2* __restrict__ w,
               float* __restrict__ out,
               int batch_stride)
{
    __shared__ float2 smA[PAIRS_PER_BLOCK][SPAD];
    __shared__ float2 smB[PAIRS_PER_BLOCK][SPAD];

    const int tid = threadIdx.x;
    const int r = tid >> 6;      // batch-pair within block -> batches 2r, 2r+1
    const int j = tid & 63;      // butterfly index within row

    const int hl = blockIdx.x;   // (h,l) index
    const long long base = (long long)hl * D;
    const float* __restrict__ x0 = x + base + (long long)(2 * r) * batch_stride;
    const float* __restrict__ x1 = x0 + batch_stride;
    float* __restrict__ o0 = out + base + (long long)(2 * r) * batch_stride;
    float* __restrict__ o1 = o0 + batch_stride;
    const float2* __restrict__ wrow = w + base;

    float2* bufA = smA[r];
    float2* bufB = smB[r];

    float2 a[8], b[8];

    // ------------- forward FFT of z = x0 + i*x1 -------------
    // stage 0 (L=1): global read, butterfly, write bufA[8j+t]
#pragma unroll
    for (int m = 0; m < 8; m++) a[m] = make_float2(x0[j + 64 * m], x1[j + 64 * m]);
    dft8<-1>(a, b);
#pragma unroll
    for (int t = 0; t < 8; t++) bufA[pad(8 * j + t)] = b[t];
    __syncthreads();

    // stage 1 (L=8): read bufA[j+64m], write bufB[(j/8)*64 + (j%8) + 8t]
#pragma unroll
    for (int m = 0; m < 8; m++) a[m] = bufA[pad(j + 64 * m)];
    {
        int k = j & 7;
        twiddle8<-1>(a, k, 6.2831853071795865f / 64.0f);
        dft8<-1>(a, b);
        int blk = j >> 3;
#pragma unroll
        for (int t = 0; t < 8; t++) bufB[pad(blk * 64 + k + 8 * t)] = b[t];
    }
    __syncthreads();

    // stage 2 (L=64): read bufB[j+64m] -> Z[j+64t] in registers
#pragma unroll
    for (int m = 0; m < 8; m++) a[m] = bufB[pad(j + 64 * m)];
    twiddle8<-1>(a, j, 6.2831853071795865f / 512.0f);
    dft8<-1>(a, b);   // b[t] = Z[j + 64t]

    // ------------- spectral gating (registers) -------------
    // Weff'[k] = W[k] + conj(W[(512-k)&511])  (the 0.5 is folded into final scale)
#pragma unroll
    for (int t = 0; t < 8; t++) {
        int k = j + 64 * t;
        int kc = (D - k) & (D - 1);
        float2 wk = wrow[k];
        float2 wkc = wrow[kc];
        float2 weff = make_float2(wk.x + wkc.x, wk.y - wkc.y);
        a[t] = cmul(weff, b[t]);
    }

    // ------------- inverse FFT -------------
    // stage 0: write bufA (safe: everyone read bufA before the stage-1 barrier)
    dft8<1>(a, b);
#pragma unroll
    for (int t = 0; t < 8; t++) bufA[pad(8 * j + t)] = b[t];
    __syncthreads();

    // stage 1: read bufA, write bufB
#pragma unroll
    for (int m = 0; m < 8; m++) a[m] = bufA[pad(j + 64 * m)];
    {
        int k = j & 7;
        twiddle8<1>(a, k, 6.2831853071795865f / 64.0f);
        dft8<1>(a, b);
        int blk = j >> 3;
#pragma unroll
        for (int t = 0; t < 8; t++) bufB[pad(blk * 64 + k + 8 * t)] = b[t];
    }
    __syncthreads();

    // stage 2: read bufB, final butterfly, store Re->o0, Im->o1 (scale 1/1024)
#pragma unroll
    for (int m = 0; m < 8; m++) a[m] = bufB[pad(j + 64 * m)];
    twiddle8<1>(a, j, 6.2831853071795865f / 512.0f);
    dft8<1>(a, b);
#pragma unroll
    for (int t = 0; t < 8; t++) {
        o0[j + 64 * t] = b[t].x * (1.0f / 1024.0f);
        o1[j + 64 * t] = b[t].y * (1.0f / 1024.0f);
    }
}

extern "C" void kernel_launch(void* const* d_in, const int* in_sizes, int n_in,
                              void* d_out, int out_size) {
    (void)n_in; (void)out_size;
    const float* x = (const float*)d_in[0];
    // d_in[1] = mask (unused)
    const float2* w = (const float2*)d_in[2];
    float* out = (float*)d_out;

    const int wrows = (in_sizes[2] / 2) / D;   // H*L = 16384
    const int batch_stride = wrows * D;

    sgn_fft_kernel<<<wrows, THREADS>>>(x, w, out, batch_stride);
}

// round 4
// speedup vs baseline: 2.4235x; 1.2449x over previous
#include <cuda_runtime.h>

// SpectralGatingNetwork: out = Re(IFFT( W .* FFT(x, axis=-1) ))
// Real-packing: z = x[b0] + i*x[b1], gate by conjugate-symmetric
// Weff[k] = 0.5*(W[k] + conj(W[(N-k)%N])) => y0 = Re, y1 = Im.
// Radix-8 Stockham, 64 threads/pair, 4 pairs (8 batches) per CTA, one CTA per (h,l).
// Conflict-free shared padding: pad(i) = i + ((i>>3) & ~1)  (all stores AND loads clean).
// Weff computed once per CTA into shared.

#define D 512
#define PAIRS_PER_BLOCK 4
#define THREADS (64 * PAIRS_PER_BLOCK)
#define SPAD 576

__device__ __forceinline__ float2 cadd(float2 a, float2 b) { return make_float2(a.x + b.x, a.y + b.y); }
__device__ __forceinline__ float2 csub(float2 a, float2 b) { return make_float2(a.x - b.x, a.y - b.y); }
__device__ __forceinline__ float2 cmul(float2 a, float2 b) {
    return make_float2(fmaf(a.x, b.x, -a.y * b.y), fmaf(a.x, b.y, a.y * b.x));
}

template <int S>
__device__ __forceinline__ float2 mulJ(float2 z) {
    return (S < 0) ? make_float2(z.y, -z.x) : make_float2(-z.y, z.x);
}

template <int S>
__device__ __forceinline__ void dft4(float2 x0, float2 x1, float2 x2, float2 x3, float2 o[4]) {
    float2 e0 = cadd(x0, x2), e1 = csub(x0, x2);
    float2 d0 = cadd(x1, x3), d1 = csub(x1, x3);
    o[0] = cadd(e0, d0);
    o[2] = csub(e0, d0);
    float2 jd1 = mulJ<S>(d1);
    o[1] = cadd(e1, jd1);
    o[3] = csub(e1, jd1);
}

template <int S>
__device__ __forceinline__ void dft8(const float2 a[8], float2 b[8]) {
    float2 e[4], o[4];
    dft4<S>(a[0], a[2], a[4], a[6], e);
    dft4<S>(a[1], a[3], a[5], a[7], o);
    const float r2 = 0.70710678118654752f;
    const float2 w1 = make_float2(r2, S * r2);
    const float2 w3 = make_float2(-r2, S * r2);
    float2 u1 = cmul(o[1], w1);
    float2 u2 = mulJ<S>(o[2]);
    float2 u3 = cmul(o[3], w3);
    b[0] = cadd(e[0], o[0]); b[4] = csub(e[0], o[0]);
    b[1] = cadd(e[1], u1);   b[5] = csub(e[1], u1);
    b[2] = cadd(e[2], u2);   b[6] = csub(e[2], u2);
    b[3] = cadd(e[3], u3);   b[7] = csub(e[3], u3);
}

// a[m] *= exp(S * i * two_pi_over_M * k * m), log-depth power construction
template <int S>
__device__ __forceinline__ void twiddle8(float2 a[8], int k, float two_pi_over_M) {
    float ang = (float)S * two_pi_over_M * (float)k;
    float s1, c1, s4, c4;
    __sincosf(ang, &s1, &c1);
    __sincosf(4.0f * ang, &s4, &c4);
    float2 w1 = make_float2(c1, s1);
    float2 w4 = make_float2(c4, s4);
    float2 w2 = cmul(w1, w1);
    float2 w3 = cmul(w2, w1);
    float2 w5 = cmul(w4, w1);
    float2 w6 = cmul(w4, w2);
    float2 w7 = cmul(w4, w3);
    a[1] = cmul(a[1], w1);
    a[2] = cmul(a[2], w2);
    a[3] = cmul(a[3], w3);
    a[4] = cmul(a[4], w4);
    a[5] = cmul(a[5], w5);
    a[6] = cmul(a[6], w6);
    a[7] = cmul(a[7], w7);
}

// Conflict-free for both access patterns (stores 8j+t / 72blk+.. and loads j+64m)
__device__ __forceinline__ int pad(int i) { return i + ((i >> 3) & ~1); }

__global__ void __launch_bounds__(THREADS, 4)
sgn_fft_kernel(const float* __restrict__ x,
               const float2* __restrict__ w,
               float* __restrict__ out,
               int batch_stride)
{
    __shared__ float2 smA[PAIRS_PER_BLOCK][SPAD];
    __shared__ float2 smB[PAIRS_PER_BLOCK][SPAD];
    __shared__ float2 weff_sh[D];

    const int tid = threadIdx.x;
    const int r = tid >> 6;      // batch-pair within block -> batches 2r, 2r+1
    const int j = tid & 63;      // butterfly index within row

    const int hl = blockIdx.x;   // (h,l) index
    const long long base = (long long)hl * D;
    const float2* __restrict__ wrow = w + base;

    // ---- Weff = W[k] + conj(W[(512-k)&511]) (once per CTA; 0.5 folded into final scale)
#pragma unroll
    for (int k = tid; k < D; k += THREADS) {
        int kc = (D - k) & (D - 1);
        float2 wk = wrow[k];
        float2 wkc = wrow[kc];
        weff_sh[k] = make_float2(wk.x + wkc.x, wk.y - wkc.y);
    }

    const float* __restrict__ x0 = x + base + (long long)(2 * r) * batch_stride;
    const float* __restrict__ x1 = x0 + batch_stride;
    float* __restrict__ o0 = out + base + (long long)(2 * r) * batch_stride;
    float* __restrict__ o1 = o0 + batch_stride;

    float2* bufA = smA[r];
    float2* bufB = smB[r];

    float2 a[8], b[8];

    // ------------- forward FFT of z = x0 + i*x1 -------------
    // stage 0 (L=1): global read, butterfly, write bufA[8j+t]
#pragma unroll
    for (int m = 0; m < 8; m++) a[m] = make_float2(x0[j + 64 * m], x1[j + 64 * m]);
    dft8<-1>(a, b);
#pragma unroll
    for (int t = 0; t < 8; t++) bufA[pad(8 * j + t)] = b[t];
    __syncthreads();   // also covers weff_sh

    // stage 1 (L=8): read bufA[j+64m], write bufB[(j/8)*64 + (j%8) + 8t]
#pragma unroll
    for (int m = 0; m < 8; m++) a[m] = bufA[pad(j + 64 * m)];
    {
        int k = j & 7;
        twiddle8<-1>(a, k, 6.2831853071795865f / 64.0f);
        dft8<-1>(a, b);
        int blk = j >> 3;
#pragma unroll
        for (int t = 0; t < 8; t++) bufB[pad(blk * 64 + k + 8 * t)] = b[t];
    }
    __syncthreads();

    // stage 2 (L=64): read bufB[j+64m] -> Z[j+64t] in registers
#pragma unroll
    for (int m = 0; m < 8; m++) a[m] = bufB[pad(j + 64 * m)];
    twiddle8<-1>(a, j, 6.2831853071795865f / 512.0f);
    dft8<-1>(a, b);   // b[t] = Z[j + 64t]

    // ------------- spectral gating (Weff from shared) -------------
#pragma unroll
    for (int t = 0; t < 8; t++) {
        a[t] = cmul(weff_sh[j + 64 * t], b[t]);
    }

    // ------------- inverse FFT -------------
    // stage 0: write bufA (everyone finished reading bufA before last barrier)
    dft8<1>(a, b);
#pragma unroll
    for (int t = 0; t < 8; t++) bufA[pad(8 * j + t)] = b[t];
    __syncthreads();

    // stage 1: read bufA, write bufB
#pragma unroll
    for (int m = 0; m < 8; m++) a[m] = bufA[pad(j + 64 * m)];
    {
        int k = j & 7;
        twiddle8<1>(a, k, 6.2831853071795865f / 64.0f);
        dft8<1>(a, b);
        int blk = j >> 3;
#pragma unroll
        for (int t = 0; t < 8; t++) bufB[pad(blk * 64 + k + 8 * t)] = b[t];
    }
    __syncthreads();

    // stage 2: read bufB, final butterfly, store Re->o0, Im->o1 (scale 1/1024)
#pragma unroll
    for (int m = 0; m < 8; m++) a[m] = bufB[pad(j + 64 * m)];
    twiddle8<1>(a, j, 6.2831853071795865f / 512.0f);
    dft8<1>(a, b);
#pragma unroll
    for (int t = 0; t < 8; t++) {
        o0[j + 64 * t] = b[t].x * (1.0f / 1024.0f);
        o1[j + 64 * t] = b[t].y * (1.0f / 1024.0f);
    }
}

extern "C" void kernel_launch(void* const* d_in, const int* in_sizes, int n_in,
                              void* d_out, int out_size) {
    (void)n_in; (void)out_size;
    const float* x = (const float*)d_in[0];
    // d_in[1] = mask (unused)
    const float2* w = (const float2*)d_in[2];
    float* out = (float*)d_out;

    const int wrows = (in_sizes[2] / 2) / D;   // H*L = 16384
    const int batch_stride = wrows * D;

    sgn_fft_kernel<<<wrows, THREADS>>>(x, w, out, batch_stride);
}

// round 5
// speedup vs baseline: 2.4418x; 1.0076x over previous
#include <cuda_runtime.h>

// SpectralGatingNetwork: out = Re(IFFT( W .* FFT(x, axis=-1) ))
// Real-packing: z = x[b0] + i*x[b1], gate by conjugate-symmetric
// Weff[k] = 0.5*(W[k] + conj(W[(N-k)%N])) => y0 = Re, y1 = Im.
// Radix-8 Stockham, 64 threads/pair, 4 pairs (8 batches) per CTA, one CTA per (h,l).
// pad(i) = i + ((i>>3) & ~1): conflict-free for all patterns AND keeps stage-0
// stores contiguous (vectorized as STS.128). Pair-local named barriers.

#define D 512
#define PAIRS_PER_BLOCK 4
#define THREADS (64 * PAIRS_PER_BLOCK)
#define SPAD 576

// pair-local barrier: 64 threads (2 warps), ids 1..4
#define BAR_PAIR(id) asm volatile("bar.sync %0, 64;" :: "r"(id) : "memory")

__device__ __forceinline__ float2 cadd(float2 a, float2 b) { return make_float2(a.x + b.x, a.y + b.y); }
__device__ __forceinline__ float2 csub(float2 a, float2 b) { return make_float2(a.x - b.x, a.y - b.y); }
__device__ __forceinline__ float2 cmul(float2 a, float2 b) {
    return make_float2(fmaf(a.x, b.x, -a.y * b.y), fmaf(a.x, b.y, a.y * b.x));
}

template <int S>
__device__ __forceinline__ float2 mulJ(float2 z) {
    return (S < 0) ? make_float2(z.y, -z.x) : make_float2(-z.y, z.x);
}

template <int S>
__device__ __forceinline__ void dft4(float2 x0, float2 x1, float2 x2, float2 x3, float2 o[4]) {
    float2 e0 = cadd(x0, x2), e1 = csub(x0, x2);
    float2 d0 = cadd(x1, x3), d1 = csub(x1, x3);
    o[0] = cadd(e0, d0);
    o[2] = csub(e0, d0);
    float2 jd1 = mulJ<S>(d1);
    o[1] = cadd(e1, jd1);
    o[3] = csub(e1, jd1);
}

template <int S>
__device__ __forceinline__ void dft8(const float2 a[8], float2 b[8]) {
    float2 e[4], o[4];
    dft4<S>(a[0], a[2], a[4], a[6], e);
    dft4<S>(a[1], a[3], a[5], a[7], o);
    const float r2 = 0.70710678118654752f;
    const float2 w1 = make_float2(r2, S * r2);
    const float2 w3 = make_float2(-r2, S * r2);
    float2 u1 = cmul(o[1], w1);
    float2 u2 = mulJ<S>(o[2]);
    float2 u3 = cmul(o[3], w3);
    b[0] = cadd(e[0], o[0]); b[4] = csub(e[0], o[0]);
    b[1] = cadd(e[1], u1);   b[5] = csub(e[1], u1);
    b[2] = cadd(e[2], u2);   b[6] = csub(e[2], u2);
    b[3] = cadd(e[3], u3);   b[7] = csub(e[3], u3);
}

// a[m] *= exp(S * i * two_pi_over_M * k * m), log-depth power construction
template <int S>
__device__ __forceinline__ void twiddle8(float2 a[8], int k, float two_pi_over_M) {
    float ang = (float)S * two_pi_over_M * (float)k;
    float s1, c1, s4, c4;
    __sincosf(ang, &s1, &c1);
    __sincosf(4.0f * ang, &s4, &c4);
    float2 w1 = make_float2(c1, s1);
    float2 w4 = make_float2(c4, s4);
    float2 w2 = cmul(w1, w1);
    float2 w3 = cmul(w2, w1);
    float2 w5 = cmul(w4, w1);
    float2 w6 = cmul(w4, w2);
    float2 w7 = cmul(w4, w3);
    a[1] = cmul(a[1], w1);
    a[2] = cmul(a[2], w2);
    a[3] = cmul(a[3], w3);
    a[4] = cmul(a[4], w4);
    a[5] = cmul(a[5], w5);
    a[6] = cmul(a[6], w6);
    a[7] = cmul(a[7], w7);
}

// Conflict-free for stores 8j+t / 72blk and loads j+64m; keeps 8j+t contiguous.
__device__ __forceinline__ int pad(int i) { return i + ((i >> 3) & ~1); }

// store b[0..7] to 8 contiguous float2 slots starting at base (16B aligned)
__device__ __forceinline__ void store8_vec(float2* base, const float2 b[8]) {
    float4* p = reinterpret_cast<float4*>(base);
    p[0] = make_float4(b[0].x, b[0].y, b[1].x, b[1].y);
    p[1] = make_float4(b[2].x, b[2].y, b[3].x, b[3].y);
    p[2] = make_float4(b[4].x, b[4].y, b[5].x, b[5].y);
    p[3] = make_float4(b[6].x, b[6].y, b[7].x, b[7].y);
}

__global__ void __launch_bounds__(THREADS, 4)
sgn_fft_kernel(const float* __restrict__ x,
               const float2* __restrict__ w,
               float* __restrict__ out,
               int batch_stride)
{
    __shared__ float2 smA[PAIRS_PER_BLOCK][SPAD];
    __shared__ float2 smB[PAIRS_PER_BLOCK][SPAD];
    __shared__ float2 weff_sh[D];

    const int tid = threadIdx.x;
    const int r = tid >> 6;      // batch-pair within block -> batches 2r, 2r+1
    const int j = tid & 63;      // butterfly index within row
    const int barid = r + 1;     // named barrier id for this pair

    const int hl = blockIdx.x;   // (h,l) index
    const long long base = (long long)hl * D;
    const float2* __restrict__ wrow = w + base;

    // ---- Weff = (W[k] + conj(W[(512-k)&511])) * (1/1024); 0.5 and IFFT 1/512 folded
#pragma unroll
    for (int k = tid; k < D; k += THREADS) {
        int kc = (D - k) & (D - 1);
        float2 wk = wrow[k];
        float2 wkc = wrow[kc];
        weff_sh[k] = make_float2((wk.x + wkc.x) * (1.0f / 1024.0f),
                                 (wk.y - wkc.y) * (1.0f / 1024.0f));
    }

    const float* __restrict__ x0 = x + base + (long long)(2 * r) * batch_stride;
    const float* __restrict__ x1 = x0 + batch_stride;
    float* __restrict__ o0 = out + base + (long long)(2 * r) * batch_stride;
    float* __restrict__ o1 = o0 + batch_stride;

    float2* bufA = smA[r];
    float2* bufB = smB[r];

    float2 a[8], b[8];

    // ------------- forward FFT of z = x0 + i*x1 -------------
    // stage 0 (L=1): global read, butterfly, vectorized store bufA[8j..8j+7]
#pragma unroll
    for (int m = 0; m < 8; m++) a[m] = make_float2(x0[j + 64 * m], x1[j + 64 * m]);
    dft8<-1>(a, b);
    store8_vec(&bufA[pad(8 * j)], b);
    __syncthreads();   // CTA-wide: also covers weff_sh

    // stage 1 (L=8): read bufA[j+64m], write bufB[(j/8)*64 + (j%8) + 8t]
#pragma unroll
    for (int m = 0; m < 8; m++) a[m] = bufA[pad(j + 64 * m)];
    {
        int k = j & 7;
        twiddle8<-1>(a, k, 6.2831853071795865f / 64.0f);
        dft8<-1>(a, b);
        int blk = j >> 3;
#pragma unroll
        for (int t = 0; t < 8; t++) bufB[pad(blk * 64 + k + 8 * t)] = b[t];
    }
    BAR_PAIR(barid);

    // stage 2 (L=64): read bufB[j+64m] -> Z[j+64t] in registers
#pragma unroll
    for (int m = 0; m < 8; m++) a[m] = bufB[pad(j + 64 * m)];
    twiddle8<-1>(a, j, 6.2831853071795865f / 512.0f);
    dft8<-1>(a, b);   // b[t] = Z[j + 64t]

    // ------------- spectral gating (Weff from shared, scale pre-folded) -------------
#pragma unroll
    for (int t = 0; t < 8; t++) {
        a[t] = cmul(weff_sh[j + 64 * t], b[t]);
    }

    // ------------- inverse FFT -------------
    // stage 0: vectorized store bufA (pair finished reading bufA before BAR_PAIR)
    dft8<1>(a, b);
    store8_vec(&bufA[pad(8 * j)], b);
    BAR_PAIR(barid);

    // stage 1: read bufA, write bufB
#pragma unroll
    for (int m = 0; m < 8; m++) a[m] = bufA[pad(j + 64 * m)];
    {
        int k = j & 7;
        twiddle8<1>(a, k, 6.2831853071795865f / 64.0f);
        dft8<1>(a, b);
        int blk = j >> 3;
#pragma unroll
        for (int t = 0; t < 8; t++) bufB[pad(blk * 64 + k + 8 * t)] = b[t];
    }
    BAR_PAIR(barid);

    // stage 2: read bufB, final butterfly, store Re->o0, Im->o1 (already scaled)
#pragma unroll
    for (int m = 0; m < 8; m++) a[m] = bufB[pad(j + 64 * m)];
    twiddle8<1>(a, j, 6.2831853071795865f / 512.0f);
    dft8<1>(a, b);
#pragma unroll
    for (int t = 0; t < 8; t++) {
        o0[j + 64 * t] = b[t].x;
        o1[j + 64 * t] = b[t].y;
    }
}

extern "C" void kernel_launch(void* const* d_in, const int* in_sizes, int n_in,
                              void* d_out, int out_size) {
    (void)n_in; (void)out_size;
    const float* x = (const float*)d_in[0];
    // d_in[1] = mask (unused)
    const float2* w = (const float2*)d_in[2];
    float* out = (float*)d_out;

    const int wrows = (in_sizes[2] / 2) / D;   // H*L = 16384
    const int batch_stride = wrows * D;

    sgn_fft_kernel<<<wrows, THREADS>>>(x, w, out, batch_stride);
}

// round 6
// speedup vs baseline: 2.4424x; 1.0002x over previous
#include <cuda_runtime.h>

// SpectralGatingNetwork: out = Re(IFFT( W .* FFT(x, axis=-1) ))
// Real-packing: z = x[b0] + i*x[b1], gate by conjugate-symmetric
// Weff[k] = 0.5*(W[k] + conj(W[(N-k)%N])) => y0 = Re, y1 = Im.
// Radix-8 Stockham, 64 threads/pair, 4 pairs (8 batches) per CTA, one CTA per (h,l).
// pad(i) = i + ((i>>3) & ~1): conflict-free for all patterns AND keeps stage-0
// stores contiguous (vectorized as STS.128). Pair-local named barriers.

#define D 512
#define PAIRS_PER_BLOCK 4
#define THREADS (64 * PAIRS_PER_BLOCK)
#define SPAD 576

// pair-local barrier: 64 threads (2 warps), ids 1..4
#define BAR_PAIR(id) asm volatile("bar.sync %0, 64;" :: "r"(id) : "memory")

__device__ __forceinline__ float2 cadd(float2 a, float2 b) { return make_float2(a.x + b.x, a.y + b.y); }
__device__ __forceinline__ float2 csub(float2 a, float2 b) { return make_float2(a.x - b.x, a.y - b.y); }
__device__ __forceinline__ float2 cmul(float2 a, float2 b) {
    return make_float2(fmaf(a.x, b.x, -a.y * b.y), fmaf(a.x, b.y, a.y * b.x));
}

template <int S>
__device__ __forceinline__ float2 mulJ(float2 z) {
    return (S < 0) ? make_float2(z.y, -z.x) : make_float2(-z.y, z.x);
}

template <int S>
__device__ __forceinline__ void dft4(float2 x0, float2 x1, float2 x2, float2 x3, float2 o[4]) {
    float2 e0 = cadd(x0, x2), e1 = csub(x0, x2);
    float2 d0 = cadd(x1, x3), d1 = csub(x1, x3);
    o[0] = cadd(e0, d0);
    o[2] = csub(e0, d0);
    float2 jd1 = mulJ<S>(d1);
    o[1] = cadd(e1, jd1);
    o[3] = csub(e1, jd1);
}

template <int S>
__device__ __forceinline__ void dft8(const float2 a[8], float2 b[8]) {
    float2 e[4], o[4];
    dft4<S>(a[0], a[2], a[4], a[6], e);
    dft4<S>(a[1], a[3], a[5], a[7], o);
    const float r2 = 0.70710678118654752f;
    const float2 w1 = make_float2(r2, S * r2);
    const float2 w3 = make_float2(-r2, S * r2);
    float2 u1 = cmul(o[1], w1);
    float2 u2 = mulJ<S>(o[2]);
    float2 u3 = cmul(o[3], w3);
    b[0] = cadd(e[0], o[0]); b[4] = csub(e[0], o[0]);
    b[1] = cadd(e[1], u1);   b[5] = csub(e[1], u1);
    b[2] = cadd(e[2], u2);   b[6] = csub(e[2], u2);
    b[3] = cadd(e[3], u3);   b[7] = csub(e[3], u3);
}

// a[m] *= exp(S * i * two_pi_over_M * k * m), log-depth power construction
template <int S>
__device__ __forceinline__ void twiddle8(float2 a[8], int k, float two_pi_over_M) {
    float ang = (float)S * two_pi_over_M * (float)k;
    float s1, c1, s4, c4;
    __sincosf(ang, &s1, &c1);
    __sincosf(4.0f * ang, &s4, &c4);
    float2 w1 = make_float2(c1, s1);
    float2 w4 = make_float2(c4, s4);
    float2 w2 = cmul(w1, w1);
    float2 w3 = cmul(w2, w1);
    float2 w5 = cmul(w4, w1);
    float2 w6 = cmul(w4, w2);
    float2 w7 = cmul(w4, w3);
    a[1] = cmul(a[1], w1);
    a[2] = cmul(a[2], w2);
    a[3] = cmul(a[3], w3);
    a[4] = cmul(a[4], w4);
    a[5] = cmul(a[5], w5);
    a[6] = cmul(a[6], w6);
    a[7] = cmul(a[7], w7);
}

// Conflict-free for stores 8j+t / 72blk and loads j+64m; keeps 8j+t contiguous.
__device__ __forceinline__ int pad(int i) { return i + ((i >> 3) & ~1); }

// store b[0..7] to 8 contiguous float2 slots starting at base (16B aligned)
__device__ __forceinline__ void store8_vec(float2* base, const float2 b[8]) {
    float4* p = reinterpret_cast<float4*>(base);
    p[0] = make_float4(b[0].x, b[0].y, b[1].x, b[1].y);
    p[1] = make_float4(b[2].x, b[2].y, b[3].x, b[3].y);
    p[2] = make_float4(b[4].x, b[4].y, b[5].x, b[5].y);
    p[3] = make_float4(b[6].x, b[6].y, b[7].x, b[7].y);
}

__global__ void __launch_bounds__(THREADS, 4)
sgn_fft_kernel(const float* __restrict__ x,
               const float2* __restrict__ w,
               float* __restrict__ out,
               int batch_stride)
{
    __shared__ float2 smA[PAIRS_PER_BLOCK][SPAD];
    __shared__ float2 smB[PAIRS_PER_BLOCK][SPAD];
    __shared__ float2 weff_sh[D];

    const int tid = threadIdx.x;
    const int r = tid >> 6;      // batch-pair within block -> batches 2r, 2r+1
    const int j = tid & 63;      // butterfly index within row
    const int barid = r + 1;     // named barrier id for this pair

    const int hl = blockIdx.x;   // (h,l) index
    const long long base = (long long)hl * D;
    const float2* __restrict__ wrow = w + base;

    // ---- Weff = (W[k] + conj(W[(512-k)&511])) * (1/1024); 0.5 and IFFT 1/512 folded
#pragma unroll
    for (int k = tid; k < D; k += THREADS) {
        int kc = (D - k) & (D - 1);
        float2 wk = wrow[k];
        float2 wkc = wrow[kc];
        weff_sh[k] = make_float2((wk.x + wkc.x) * (1.0f / 1024.0f),
                                 (wk.y - wkc.y) * (1.0f / 1024.0f));
    }

    const float* __restrict__ x0 = x + base + (long long)(2 * r) * batch_stride;
    const float* __restrict__ x1 = x0 + batch_stride;
    float* __restrict__ o0 = out + base + (long long)(2 * r) * batch_stride;
    float* __restrict__ o1 = o0 + batch_stride;

    float2* bufA = smA[r];
    float2* bufB = smB[r];

    float2 a[8], b[8];

    // ------------- forward FFT of z = x0 + i*x1 -------------
    // stage 0 (L=1): global read, butterfly, vectorized store bufA[8j..8j+7]
#pragma unroll
    for (int m = 0; m < 8; m++) a[m] = make_float2(x0[j + 64 * m], x1[j + 64 * m]);
    dft8<-1>(a, b);
    store8_vec(&bufA[pad(8 * j)], b);
    __syncthreads();   // CTA-wide: also covers weff_sh

    // stage 1 (L=8): read bufA[j+64m], write bufB[(j/8)*64 + (j%8) + 8t]
#pragma unroll
    for (int m = 0; m < 8; m++) a[m] = bufA[pad(j + 64 * m)];
    {
        int k = j & 7;
        twiddle8<-1>(a, k, 6.2831853071795865f / 64.0f);
        dft8<-1>(a, b);
        int blk = j >> 3;
#pragma unroll
        for (int t = 0; t < 8; t++) bufB[pad(blk * 64 + k + 8 * t)] = b[t];
    }
    BAR_PAIR(barid);

    // stage 2 (L=64): read bufB[j+64m] -> Z[j+64t] in registers
#pragma unroll
    for (int m = 0; m < 8; m++) a[m] = bufB[pad(j + 64 * m)];
    twiddle8<-1>(a, j, 6.2831853071795865f / 512.0f);
    dft8<-1>(a, b);   // b[t] = Z[j + 64t]

    // ------------- spectral gating (Weff from shared, scale pre-folded) -------------
#pragma unroll
    for (int t = 0; t < 8; t++) {
        a[t] = cmul(weff_sh[j + 64 * t], b[t]);
    }

    // ------------- inverse FFT -------------
    // stage 0: vectorized store bufA (pair finished reading bufA before BAR_PAIR)
    dft8<1>(a, b);
    store8_vec(&bufA[pad(8 * j)], b);
    BAR_PAIR(barid);

    // stage 1: read bufA, write bufB
#pragma unroll
    for (int m = 0; m < 8; m++) a[m] = bufA[pad(j + 64 * m)];
    {
        int k = j & 7;
        twiddle8<1>(a, k, 6.2831853071795865f / 64.0f);
        dft8<1>(a, b);
        int blk = j >> 3;
#pragma unroll
        for (int t = 0; t < 8; t++) bufB[pad(blk * 64 + k + 8 * t)] = b[t];
    }
    BAR_PAIR(barid);

    // stage 2: read bufB, final butterfly, store Re->o0, Im->o1 (already scaled)
#pragma unroll
    for (int m = 0; m < 8; m++) a[m] = bufB[pad(j + 64 * m)];
    twiddle8<1>(a, j, 6.2831853071795865f / 512.0f);
    dft8<1>(a, b);
#pragma unroll
    for (int t = 0; t < 8; t++) {
        o0[j + 64 * t] = b[t].x;
        o1[j + 64 * t] = b[t].y;
    }
}

extern "C" void kernel_launch(void* const* d_in, const int* in_sizes, int n_in,
                              void* d_out, int out_size) {
    (void)n_in; (void)out_size;
    const float* x = (const float*)d_in[0];
    // d_in[1] = mask (unused)
    const float2* w = (const float2*)d_in[2];
    float* out = (float*)d_out;

    const int wrows = (in_sizes[2] / 2) / D;   // H*L = 16384
    const int batch_stride = wrows * D;

    sgn_fft_kernel<<<wrows, THREADS>>>(x, w, out, batch_stride);
}

// round 7
// speedup vs baseline: 2.7556x; 1.1282x over previous
#include <cuda_runtime.h>

// SpectralGatingNetwork: out = Re(IFFT( W .* FFT(x, axis=-1) ))
// Real-packing: z = x[b0] + i*x[b1], gate by conjugate-symmetric
// Weff[k] = 0.5*(W[k] + conj(W[(N-k)%N])) => y0 = Re, y1 = Im.
// Radix-8 Stockham, 64 threads/pair, 4 pairs (8 batches) per CTA, one CTA per (h,l).
// Packed f32x2 complex add/sub (Blackwell FFMA2/FADD2 path, PTX-only).

#define D 512
#define PAIRS_PER_BLOCK 4
#define THREADS (64 * PAIRS_PER_BLOCK)
#define SPAD 576

#define BAR_PAIR(id) asm volatile("bar.sync %0, 64;" :: "r"(id) : "memory")

typedef unsigned long long u64t;

__device__ __forceinline__ u64t f2u(float2 a) {
    u64t r;
    asm("mov.b64 %0, {%1, %2};" : "=l"(r) : "f"(a.x), "f"(a.y));
    return r;
}
__device__ __forceinline__ float2 u2f(u64t v) {
    float2 r;
    asm("mov.b64 {%0, %1}, %2;" : "=f"(r.x), "=f"(r.y) : "l"(v));
    return r;
}

// packed complex add: one FADD2
__device__ __forceinline__ float2 cadd(float2 a, float2 b) {
    u64t r, x = f2u(a), y = f2u(b);
    asm("add.rn.f32x2 %0, %1, %2;" : "=l"(r) : "l"(x), "l"(y));
    return u2f(r);
}
// packed complex sub: a - b as fma(b, -1, a) -> one FFMA2
__device__ __forceinline__ float2 csub(float2 a, float2 b) {
    const u64t NEG1 = 0xBF800000BF800000ULL;  // (-1.0f, -1.0f)
    u64t r, x = f2u(a), y = f2u(b);
    asm("fma.rn.f32x2 %0, %1, %2, %3;" : "=l"(r) : "l"(y), "l"(NEG1), "l"(x));
    return u2f(r);
}

__device__ __forceinline__ float2 cmul(float2 a, float2 b) {
    return make_float2(fmaf(a.x, b.x, -a.y * b.y), fmaf(a.x, b.y, a.y * b.x));
}

// scalar butterflies with +-i folded into FADD sign modifiers (free in SASS)
// S=-1: jd = (d.y, -d.x) ; S=+1: jd = (-d.y, d.x)
template <int S>
__device__ __forceinline__ void bfly_j(float2 e, float2 d, float2& lo, float2& hi) {
    if (S < 0) {
        lo = make_float2(e.x + d.y, e.y - d.x);
        hi = make_float2(e.x - d.y, e.y + d.x);
    } else {
        lo = make_float2(e.x - d.y, e.y + d.x);
        hi = make_float2(e.x + d.y, e.y - d.x);
    }
}

template <int S>
__device__ __forceinline__ void dft4(float2 x0, float2 x1, float2 x2, float2 x3, float2 o[4]) {
    float2 e0 = cadd(x0, x2), e1 = csub(x0, x2);
    float2 d0 = cadd(x1, x3), d1 = csub(x1, x3);
    o[0] = cadd(e0, d0);
    o[2] = csub(e0, d0);
    bfly_j<S>(e1, d1, o[1], o[3]);
}

template <int S>
__device__ __forceinline__ void dft8(const float2 a[8], float2 b[8]) {
    float2 e[4], o[4];
    dft4<S>(a[0], a[2], a[4], a[6], e);
    dft4<S>(a[1], a[3], a[5], a[7], o);
    const float r2 = 0.70710678118654752f;
    const float2 w1 = make_float2(r2, S * r2);
    const float2 w3 = make_float2(-r2, S * r2);
    float2 u1 = cmul(o[1], w1);
    float2 u3 = cmul(o[3], w3);
    b[0] = cadd(e[0], o[0]); b[4] = csub(e[0], o[0]);
    b[1] = cadd(e[1], u1);   b[5] = csub(e[1], u1);
    bfly_j<S>(e[2], o[2], b[2], b[6]);
    b[3] = cadd(e[3], u3);   b[7] = csub(e[3], u3);
}

// a[m] *= exp(S * i * two_pi_over_M * k * m), log-depth power construction
template <int S>
__device__ __forceinline__ void twiddle8(float2 a[8], int k, float two_pi_over_M) {
    float ang = (float)S * two_pi_over_M * (float)k;
    float s1, c1, s4, c4;
    __sincosf(ang, &s1, &c1);
    __sincosf(4.0f * ang, &s4, &c4);
    float2 w1 = make_float2(c1, s1);
    float2 w4 = make_float2(c4, s4);
    float2 w2 = cmul(w1, w1);
    float2 w3 = cmul(w2, w1);
    float2 w5 = cmul(w4, w1);
    float2 w6 = cmul(w4, w2);
    float2 w7 = cmul(w4, w3);
    a[1] = cmul(a[1], w1);
    a[2] = cmul(a[2], w2);
    a[3] = cmul(a[3], w3);
    a[4] = cmul(a[4], w4);
    a[5] = cmul(a[5], w5);
    a[6] = cmul(a[6], w6);
    a[7] = cmul(a[7], w7);
}

// Conflict-free for stores 8j+t / 72blk and loads j+64m; keeps 8j+t contiguous.
__device__ __forceinline__ int pad(int i) { return i + ((i >> 3) & ~1); }

__device__ __forceinline__ void store8_vec(float2* base, const float2 b[8]) {
    float4* p = reinterpret_cast<float4*>(base);
    p[0] = make_float4(b[0].x, b[0].y, b[1].x, b[1].y);
    p[1] = make_float4(b[2].x, b[2].y, b[3].x, b[3].y);
    p[2] = make_float4(b[4].x, b[4].y, b[5].x, b[5].y);
    p[3] = make_float4(b[6].x, b[6].y, b[7].x, b[7].y);
}

__global__ void __launch_bounds__(THREADS, 4)
sgn_fft_kernel(const float* __restrict__ x,
               const float2* __restrict__ w,
               float* __restrict__ out,
               int batch_stride)
{
    __shared__ float2 smA[PAIRS_PER_BLOCK][SPAD];
    __shared__ float2 smB[PAIRS_PER_BLOCK][SPAD];
    __shared__ float2 weff_sh[D];

    const int tid = threadIdx.x;
    const int r = tid >> 6;
    const int j = tid & 63;
    const int barid = r + 1;

    const int hl = blockIdx.x;
    const long long base = (long long)hl * D;
    const float2* __restrict__ wrow = w + base;

    // ---- Weff = (W[k] + conj(W[(512-k)&511])) * (1/1024)
#pragma unroll
    for (int k = tid; k < D; k += THREADS) {
        int kc = (D - k) & (D - 1);
        float2 wk = wrow[k];
        float2 wkc = wrow[kc];
        weff_sh[k] = make_float2((wk.x + wkc.x) * (1.0f / 1024.0f),
                                 (wk.y - wkc.y) * (1.0f / 1024.0f));
    }

    const float* __restrict__ x0 = x + base + (long long)(2 * r) * batch_stride;
    const float* __restrict__ x1 = x0 + batch_stride;
    float* __restrict__ o0 = out + base + (long long)(2 * r) * batch_stride;
    float* __restrict__ o1 = o0 + batch_stride;

    float2* bufA = smA[r];
    float2* bufB = smB[r];

    float2 a[8], b[8];

    // ------------- forward FFT of z = x0 + i*x1 -------------
#pragma unroll
    for (int m = 0; m < 8; m++) a[m] = make_float2(x0[j + 64 * m], x1[j + 64 * m]);
    dft8<-1>(a, b);
    store8_vec(&bufA[pad(8 * j)], b);
    __syncthreads();   // CTA-wide: also covers weff_sh

    // stage 1 (L=8)
#pragma unroll
    for (int m = 0; m < 8; m++) a[m] = bufA[pad(j + 64 * m)];
    {
        int k = j & 7;
        twiddle8<-1>(a, k, 6.2831853071795865f / 64.0f);
        dft8<-1>(a, b);
        int blk = j >> 3;
#pragma unroll
        for (int t = 0; t < 8; t++) bufB[pad(blk * 64 + k + 8 * t)] = b[t];
    }
    BAR_PAIR(barid);

    // stage 2 (L=64) -> Z[j+64t] in registers
#pragma unroll
    for (int m = 0; m < 8; m++) a[m] = bufB[pad(j + 64 * m)];
    twiddle8<-1>(a, j, 6.2831853071795865f / 512.0f);
    dft8<-1>(a, b);

    // ------------- spectral gating -------------
#pragma unroll
    for (int t = 0; t < 8; t++) {
        a[t] = cmul(weff_sh[j + 64 * t], b[t]);
    }

    // ------------- inverse FFT -------------
    dft8<1>(a, b);
    store8_vec(&bufA[pad(8 * j)], b);
    BAR_PAIR(barid);

#pragma unroll
    for (int m = 0; m < 8; m++) a[m] = bufA[pad(j + 64 * m)];
    {
        int k = j & 7;
        twiddle8<1>(a, k, 6.2831853071795865f / 64.0f);
        dft8<1>(a, b);
        int blk = j >> 3;
#pragma unroll
        for (int t = 0; t < 8; t++) bufB[pad(blk * 64 + k + 8 * t)] = b[t];
    }
    BAR_PAIR(barid);

#pragma unroll
    for (int m = 0; m < 8; m++) a[m] = bufB[pad(j + 64 * m)];
    twiddle8<1>(a, j, 6.2831853071795865f / 512.0f);
    dft8<1>(a, b);
#pragma unroll
    for (int t = 0; t < 8; t++) {
        o0[j + 64 * t] = b[t].x;
        o1[j + 64 * t] = b[t].y;
    }
}

extern "C" void kernel_launch(void* const* d_in, const int* in_sizes, int n_in,
                              void* d_out, int out_size) {
    (void)n_in; (void)out_size;
    const float* x = (const float*)d_in[0];
    // d_in[1] = mask (unused)
    const float2* w = (const float2*)d_in[2];
    float* out = (float*)d_out;

    const int wrows = (in_sizes[2] / 2) / D;   // H*L = 16384
    const int batch_stride = wrows * D;

    sgn_fft_kernel<<<wrows, THREADS>>>(x, w, out, batch_stride);
}